// round 8
// baseline (speedup 1.0000x reference)
#include <cuda_runtime.h>
#include <cuda_bf16.h>
#include <cstdint>

#define NN 50000
#define EE 400000
#define EPS_SKIP_F 1.000001f

// ---------------- scratch ----------------
__device__ float    g_xm[2][NN * 128];   // per-branch transformed features
__device__ float    g_ssrc[2][NN * 4];
__device__ float    g_sdst[2][NN * 4];
__device__ float    g_denom[2][NN * 4];
__device__ float    g_ebuf[2][EE * 4];
__device__ uint32_t g_Wtp[3][2][128 * 64];  // W^T split: [branch][hi/lo][n][kpair] bf16x2

// ---------------- helpers ----------------
__device__ __forceinline__ void split_pack(float v0, float v1, uint32_t& hi, uint32_t& lo) {
    __nv_bfloat16 h0 = __float2bfloat16_rn(v0);
    __nv_bfloat16 h1 = __float2bfloat16_rn(v1);
    float r0 = v0 - __bfloat162float(h0);
    float r1 = v1 - __bfloat162float(h1);
    __nv_bfloat162 hp; hp.x = h0; hp.y = h1;
    __nv_bfloat162 lp; lp.x = __float2bfloat16_rn(r0); lp.y = __float2bfloat16_rn(r1);
    hi = *(uint32_t*)&hp;
    lo = *(uint32_t*)&lp;
}

__device__ __forceinline__ void mma_bf16(float* d,
                                         uint32_t a0, uint32_t a1, uint32_t a2, uint32_t a3,
                                         uint32_t b0, uint32_t b1) {
    asm volatile(
        "mma.sync.aligned.m16n8k16.row.col.f32.bf16.bf16.f32 "
        "{%0,%1,%2,%3}, {%4,%5,%6,%7}, {%8,%9}, {%0,%1,%2,%3};"
        : "+f"(d[0]), "+f"(d[1]), "+f"(d[2]), "+f"(d[3])
        : "r"(a0), "r"(a1), "r"(a2), "r"(a3), "r"(b0), "r"(b1));
}

// ---------------- prep: W -> W^T, split to bf16 hi/lo, pack k-pairs; zero denom ----------------
__global__ void prep_b_kernel(const float* __restrict__ Wl,
                              const float* __restrict__ Wu,
                              const float* __restrict__ Ws) {
    int i = blockIdx.x * blockDim.x + threadIdx.x;
    if (i < 2 * NN * 4) ((float*)g_denom)[i] = 0.0f;
    if (i >= 3 * 8192) return;
    const int b = i / 8192;
    const int r = i & 8191;
    const int n = r >> 6, kp = r & 63;
    const float* __restrict__ W = (b == 0) ? Wl : ((b == 1) ? Wu : Ws);
    const float v0 = W[(2 * kp) * 128 + n];
    const float v1 = W[(2 * kp + 1) * 128 + n];
    uint32_t hi, lo;
    split_pack(v0, v1, hi, lo);
    g_Wtp[b][0][n * 64 + kp] = hi;
    g_Wtp[b][1][n * 64 + kp] = lo;
}

// ---------------- fused 3-branch bf16x3 GEMM + logit epilogue ----------------
// grid = (391, 2): x-tile of 128 rows, N-half of 64 cols; all 3 branches per CTA.
#define PADP 68                        // stride ≡ 4 (mod 32) -> conflict-free frag loads
#define ASZ  (128 * PADP)
#define BSZ  (64 * PADP)
#define GEMM_SMEM ((2 * ASZ + 6 * BSZ) * 4)   // Ah, Al, 3x(Bh, Bl) = 174,080 B

__global__ __launch_bounds__(256, 1) void gemm_mma_kernel(
    const float* __restrict__ x, float* __restrict__ out_skip,
    const float* __restrict__ a_sl, const float* __restrict__ a_dl,
    const float* __restrict__ a_su, const float* __restrict__ a_du)
{
    extern __shared__ uint32_t smem[];
    uint32_t* Ah = smem;
    uint32_t* Al = smem + ASZ;
    uint32_t* Bbase = smem + 2 * ASZ;   // [b][hi/lo][BSZ]

    const int nh = blockIdx.y;          // N-half: cols [nh*64, nh*64+64)
    const int bm0 = blockIdx.x * 128;

    const int t = threadIdx.x;
    const int wid = t >> 5, lane = t & 31;
    const int lg = lane >> 2;           // 0..7
    const int lt = lane & 3;            // 0..3

    // ---- load + split A tile ----
#pragma unroll
    for (int i = t; i < 4096; i += 256) {
        const int row = i >> 5;
        const int c4 = i & 31;
        const int m = bm0 + row;
        float4 v = make_float4(0.f, 0.f, 0.f, 0.f);
        if (m < NN) v = *(const float4*)&x[m * 128 + c4 * 4];
        uint32_t h0, l0, h1, l1;
        split_pack(v.x, v.y, h0, l0);
        split_pack(v.z, v.w, h1, l1);
        const int base = row * PADP + 2 * c4;
        Ah[base] = h0; Ah[base + 1] = h1;
        Al[base] = l0; Al[base + 1] = l1;
    }
    // ---- load B half-tiles for all 3 branches ----
#pragma unroll
    for (int i = t; i < 3 * 1024; i += 256) {
        const int b = i >> 10;
        const int r = i & 1023;
        const int n = r >> 4;           // 0..63 local
        const int p4 = r & 15;
        const int gn = nh * 64 + n;
        uint4 vh = *(const uint4*)&g_Wtp[b][0][gn * 64 + p4 * 4];
        uint4 vl = *(const uint4*)&g_Wtp[b][1][gn * 64 + p4 * 4];
        uint32_t* Bh = Bbase + b * 2 * BSZ;
        uint32_t* Bl = Bh + BSZ;
        *(uint4*)&Bh[n * PADP + p4 * 4] = vh;
        *(uint4*)&Bl[n * PADP + p4 * 4] = vl;
    }
    __syncthreads();

    // warp tile: 32 rows x 32 cols; 4x2 warps cover 128x64
    const int wm = (wid & 3) * 32;
    const int wn = (wid >> 2) * 32;

    float acc[3][2][4][4];
#pragma unroll
    for (int b = 0; b < 3; b++)
#pragma unroll
        for (int mt = 0; mt < 2; mt++)
#pragma unroll
            for (int nt = 0; nt < 4; nt++)
#pragma unroll
                for (int c = 0; c < 4; c++) acc[b][mt][nt][c] = 0.f;

#pragma unroll
    for (int ks = 0; ks < 8; ks++) {
        const int kp = ks * 8;
        uint32_t ah[2][4], al[2][4];
#pragma unroll
        for (int mt = 0; mt < 2; mt++) {
            const int rb = wm + mt * 16 + lg;
            const int i0 = rb * PADP + kp + lt;
            const int i1 = (rb + 8) * PADP + kp + lt;
            ah[mt][0] = Ah[i0];     al[mt][0] = Al[i0];
            ah[mt][1] = Ah[i1];     al[mt][1] = Al[i1];
            ah[mt][2] = Ah[i0 + 4]; al[mt][2] = Al[i0 + 4];
            ah[mt][3] = Ah[i1 + 4]; al[mt][3] = Al[i1 + 4];
        }
#pragma unroll
        for (int b = 0; b < 3; b++) {
            const uint32_t* Bh = Bbase + b * 2 * BSZ;
            const uint32_t* Bl = Bh + BSZ;
            uint32_t bh[4][2], bl[4][2];
#pragma unroll
            for (int nt = 0; nt < 4; nt++) {
                const int n = wn + nt * 8 + lg;
                const int i0 = n * PADP + kp + lt;
                bh[nt][0] = Bh[i0];     bl[nt][0] = Bl[i0];
                bh[nt][1] = Bh[i0 + 4]; bl[nt][1] = Bl[i0 + 4];
            }
#pragma unroll
            for (int mt = 0; mt < 2; mt++)
#pragma unroll
                for (int nt = 0; nt < 4; nt++) {
                    mma_bf16(acc[b][mt][nt], ah[mt][0], ah[mt][1], ah[mt][2], ah[mt][3],
                             bl[nt][0], bl[nt][1]);
                    mma_bf16(acc[b][mt][nt], al[mt][0], al[mt][1], al[mt][2], al[mt][3],
                             bh[nt][0], bh[nt][1]);
                    mma_bf16(acc[b][mt][nt], ah[mt][0], ah[mt][1], ah[mt][2], ah[mt][3],
                             bh[nt][0], bh[nt][1]);
                }
        }
    }

    // ---- epilogue: store xm / skip ----
#pragma unroll
    for (int b = 0; b < 3; b++) {
        float* __restrict__ out = (b == 0) ? g_xm[0] : ((b == 1) ? g_xm[1] : out_skip);
        const float scale = (b == 2) ? EPS_SKIP_F : 1.0f;
#pragma unroll
        for (int mt = 0; mt < 2; mt++) {
            const int m0 = bm0 + wm + mt * 16 + lg;
            const int m1 = m0 + 8;
#pragma unroll
            for (int nt = 0; nt < 4; nt++) {
                const int col = nh * 64 + wn + nt * 8 + 2 * lt;
                if (m0 < NN) {
                    float2 v = make_float2(acc[b][mt][nt][0] * scale, acc[b][mt][nt][1] * scale);
                    *(float2*)&out[m0 * 128 + col] = v;
                }
                if (m1 < NN) {
                    float2 v = make_float2(acc[b][mt][nt][2] * scale, acc[b][mt][nt][3] * scale);
                    *(float2*)&out[m1 * 128 + col] = v;
                }
            }
        }
    }

    // ---- fused logit epilogue (branches 0,1): each warp owns exactly one head ----
    const int h = nh * 2 + (wn >> 5);
#pragma unroll
    for (int b = 0; b < 2; b++) {
        const float* __restrict__ asrc = (b == 0) ? a_sl : a_su;
        const float* __restrict__ adst = (b == 0) ? a_dl : a_du;
        float ssum[4] = {0.f, 0.f, 0.f, 0.f};
        float dsum[4] = {0.f, 0.f, 0.f, 0.f};
#pragma unroll
        for (int nt = 0; nt < 4; nt++) {
            const int ai = h * 32 + nt * 8 + 2 * lt;
            const float s0 = asrc[ai], s1 = asrc[ai + 1];
            const float d0 = adst[ai], d1 = adst[ai + 1];
#pragma unroll
            for (int mt = 0; mt < 2; mt++) {
                ssum[mt * 2 + 0] += acc[b][mt][nt][0] * s0 + acc[b][mt][nt][1] * s1;
                ssum[mt * 2 + 1] += acc[b][mt][nt][2] * s0 + acc[b][mt][nt][3] * s1;
                dsum[mt * 2 + 0] += acc[b][mt][nt][0] * d0 + acc[b][mt][nt][1] * d1;
                dsum[mt * 2 + 1] += acc[b][mt][nt][2] * d0 + acc[b][mt][nt][3] * d1;
            }
        }
#pragma unroll
        for (int d = 1; d <= 2; d <<= 1)
#pragma unroll
            for (int rr = 0; rr < 4; rr++) {
                ssum[rr] += __shfl_xor_sync(0xFFFFFFFF, ssum[rr], d);
                dsum[rr] += __shfl_xor_sync(0xFFFFFFFF, dsum[rr], d);
            }
        if (lt == 0) {
#pragma unroll
            for (int rr = 0; rr < 4; rr++) {
                const int row = bm0 + wm + ((rr & 1) ? 8 : 0) + ((rr >> 1) ? 16 : 0) + lg;
                if (row < NN) {
                    g_ssrc[b][row * 4 + h] = ssum[rr];
                    g_sdst[b][row * 4 + h] = dsum[rr];
                }
            }
        }
    }
}

// ---------------- attention pipeline ----------------
__device__ __forceinline__ float lrelu_exp(float a) {
    a = (a > 0.f) ? a : 0.01f * a;
    return __expf(a);
}

__global__ void pass1_kernel(const int* __restrict__ t0, const int* __restrict__ s0,
                             const int* __restrict__ t1, const int* __restrict__ s1)
{
    int idx = blockIdx.x * blockDim.x + threadIdx.x;
    if (idx >= 2 * EE) return;
    const int branch = (idx >= EE) ? 1 : 0;
    const int e = idx - branch * EE;
    const int tgt = (branch ? t1 : t0)[e];
    const int src = (branch ? s1 : s0)[e];
    float4 ss = *(const float4*)&g_ssrc[branch][src * 4];
    float4 sd = *(const float4*)&g_sdst[branch][tgt * 4];
    float ex = lrelu_exp(ss.x + sd.x);
    float ey = lrelu_exp(ss.y + sd.y);
    float ez = lrelu_exp(ss.z + sd.z);
    float ew = lrelu_exp(ss.w + sd.w);
    *(float4*)&g_ebuf[branch][e * 4] = make_float4(ex, ey, ez, ew);
    float* p = &g_denom[branch][tgt * 4];
    asm volatile("red.global.add.v4.f32 [%0], {%1,%2,%3,%4};"
                 :: "l"(p), "f"(ex), "f"(ey), "f"(ez), "f"(ew) : "memory");
}

__global__ void pass2_kernel(const int* __restrict__ t0, const int* __restrict__ s0,
                             const int* __restrict__ t1, const int* __restrict__ s1,
                             float* __restrict__ out)
{
    const int gw = (blockIdx.x * blockDim.x + threadIdx.x) >> 5;
    if (gw >= 2 * EE) return;
    const int lane = threadIdx.x & 31;
    const int branch = (gw >= EE) ? 1 : 0;
    const int e = gw - branch * EE;
    const int tgt = (branch ? t1 : t0)[e];
    const int src = (branch ? s1 : s0)[e];
    const int h = lane >> 3;
    const float eh = g_ebuf[branch][e * 4 + h];
    const float dh = g_denom[branch][tgt * 4 + h];
    const float w = eh / (dh + 1e-16f);
    const float4 v = *(const float4*)&g_xm[branch][src * 128 + lane * 4];
    float* p = &out[tgt * 128 + lane * 4];
    asm volatile("red.global.add.v4.f32 [%0], {%1,%2,%3,%4};"
                 :: "l"(p), "f"(v.x * w), "f"(v.y * w), "f"(v.z * w), "f"(v.w * w)
                 : "memory");
}

__global__ void relu_kernel(float* __restrict__ out) {
    int i = blockIdx.x * blockDim.x + threadIdx.x;
    if (i < NN * 32) {
        float4* p = (float4*)out + i;
        float4 v = *p;
        v.x = fmaxf(v.x, 0.f); v.y = fmaxf(v.y, 0.f);
        v.z = fmaxf(v.z, 0.f); v.w = fmaxf(v.w, 0.f);
        *p = v;
    }
}

// ---------------- launch ----------------
extern "C" void kernel_launch(void* const* d_in, const int* in_sizes, int n_in,
                              void* d_out, int out_size)
{
    const float* x      = (const float*)d_in[0];
    const float* W_low  = (const float*)d_in[1];
    const float* a_sl   = (const float*)d_in[2];
    const float* a_dl   = (const float*)d_in[3];
    const float* W_up   = (const float*)d_in[4];
    const float* a_su   = (const float*)d_in[5];
    const float* a_du   = (const float*)d_in[6];
    const float* W_skip = (const float*)d_in[7];
    const int* lower_tgt = (const int*)d_in[8];
    const int* lower_src = (const int*)d_in[9];
    const int* upper_tgt = (const int*)d_in[10];
    const int* upper_src = (const int*)d_in[11];
    float* out = (float*)d_out;

    static bool attr_set = false;
    if (!attr_set) {
        cudaFuncSetAttribute(gemm_mma_kernel,
                             cudaFuncAttributeMaxDynamicSharedMemorySize, GEMM_SMEM);
        attr_set = true;
    }

    // 1. prep (split/transpose W) + zero denominators
    prep_b_kernel<<<(2 * NN * 4 + 255) / 256, 256>>>(W_low, W_up, W_skip);

    // 2. fused 3-branch GEMM + logit epilogue
    dim3 ggrid((NN + 127) / 128, 2);
    gemm_mma_kernel<<<ggrid, 256, GEMM_SMEM>>>(x, out, a_sl, a_dl, a_su, a_du);

    // 3. edge softmax numerators + denominators
    pass1_kernel<<<(2 * EE + 255) / 256, 256>>>(lower_tgt, lower_src, upper_tgt, upper_src);

    // 4. weighted aggregation (warp per edge, vector REDs)
    {
        long long threads = (long long)2 * EE * 32;
        int blocks = (int)((threads + 255) / 256);
        pass2_kernel<<<blocks, 256>>>(lower_tgt, lower_src, upper_tgt, upper_src, out);
    }

    // 5. final relu (vectorized)
    relu_kernel<<<(NN * 32 + 255) / 256, 256>>>(out);
}